// round 13
// baseline (speedup 1.0000x reference)
#include <cuda_runtime.h>
#include <cuda_bf16.h>
#include <cstdint>

// Problem constants
#define Bq 2
#define Sq 2048
#define Eq 768
#define Hq 12
#define Gq 4
#define Dq 64
#define Tq 512   // Sq / Gq

#define EEc  ((size_t)Eq * Eq)
#define BTEc ((size_t)Bq * Tq * Eq)
#define BSEc ((size_t)Bq * Sq * Eq)

// ---------------------------------------------------------------------------
// Scratch (device globals)
// ---------------------------------------------------------------------------
__device__ float g_wc[4 * EEc];                        // composed f32: v g0..3
__device__ __nv_bfloat16 g_wcb[8 * EEc];               // composed bf16: [k g0..3 | q g0..3]
__device__ float g_bc[12 * Eq];                        // composed biases [q|k|v]
__device__ __nv_bfloat16 g_qib[(size_t)Gq*Bq*Tq*Eq];   // qi bf16
__device__ __nv_bfloat16 g_kib[(size_t)Gq*Bq*Sq*Eq];   // ki bf16
__device__ float g_vi [(size_t)Gq*Bq*Sq*Eq];           // vi fp32
__device__ float g_ctx[(size_t)Gq*Bq*Tq*Eq];           // ctx fp32

// ---------------------------------------------------------------------------
// helpers
// ---------------------------------------------------------------------------
__device__ __forceinline__ float f2tf32(float x) {
    uint32_t r;
    asm("cvt.rna.tf32.f32 %0, %1;" : "=r"(r) : "f"(x));
    return __uint_as_float(r);
}
__device__ __forceinline__ float4 f2tf32_4(float4 v) {
    return make_float4(f2tf32(v.x), f2tf32(v.y), f2tf32(v.z), f2tf32(v.w));
}
__device__ __forceinline__ void mma_tf32(float (&d)[4], const float a[4], const float b[2]) {
    asm volatile(
        "mma.sync.aligned.m16n8k8.row.col.f32.tf32.tf32.f32 "
        "{%0,%1,%2,%3}, {%4,%5,%6,%7}, {%8,%9}, {%0,%1,%2,%3};\n"
        : "+f"(d[0]), "+f"(d[1]), "+f"(d[2]), "+f"(d[3])
        : "r"(__float_as_uint(a[0])), "r"(__float_as_uint(a[1])),
          "r"(__float_as_uint(a[2])), "r"(__float_as_uint(a[3])),
          "r"(__float_as_uint(b[0])), "r"(__float_as_uint(b[1])));
}
__device__ __forceinline__ void mma_bf16(float (&d)[4], const uint32_t a[4], const uint32_t b[2]) {
    asm volatile(
        "mma.sync.aligned.m16n8k16.row.col.f32.bf16.bf16.f32 "
        "{%0,%1,%2,%3}, {%4,%5,%6,%7}, {%8,%9}, {%0,%1,%2,%3};\n"
        : "+f"(d[0]), "+f"(d[1]), "+f"(d[2]), "+f"(d[3])
        : "r"(a[0]), "r"(a[1]), "r"(a[2]), "r"(a[3]),
          "r"(b[0]), "r"(b[1]));
}
__device__ __forceinline__ uint32_t packbf(float lo, float hi) {
    uint32_t r;
    asm("cvt.rn.bf16x2.f32 %0, %1, %2;" : "=r"(r) : "f"(hi), "f"(lo));
    return r;
}

// ---------------------------------------------------------------------------
// Unified tf32 GEMM, 128 thr / 4 warps, 128m x 128n tile, warp 64x64.
// DOUBLE-BUFFERED smem, ONE __syncthreads per 16-k chunk.
// MODE 0 (compose, z 0..11): sel0 wcb_q(bf16, slot 4+g), sel1 wcb_k(bf16, slot g),
//                            sel2 wc_v(f32, slot g). W read [k][n] coalesced.
// MODE 1 (vi, z 0..3): vi(f32) = value @ wc_v[g] + bc_v
// MODE 2 (out, z 0..3): out = scatter_g(ctx[z] @ Wout[z].T + bout[z])
// ---------------------------------------------------------------------------
#define GS 20
#define WKN 132

template<int MODE>
__global__ __launch_bounds__(128)
void gemm_k(const float* __restrict__ P0, const float* __restrict__ P1,
            const float* __restrict__ P2, const float* __restrict__ P3,
            const float* __restrict__ P4, const float* __restrict__ P5,
            float* __restrict__ O0, float* __restrict__ O1, float* __restrict__ O2)
{
    __shared__ float As[2][128 * GS];   // 20 KB
    __shared__ float Ws[2][128 * GS];   // 20 KB (MODE0 uses 16*132=2112 per buf)

    const int z = blockIdx.z;
    const int sel = z >> 2, g = z & 3;

    const float* Ab; const float* Wb; const float* bb = nullptr;
    float* Cb = nullptr; __nv_bfloat16* Cb16 = nullptr;
    bool cmap = false, bfout = false;
    if (MODE == 0) {
        Ab = (sel == 0 ? P0 : sel == 1 ? P1 : P2) + (size_t)g * EEc;
        Wb = (sel == 0 ? P3 : sel == 1 ? P4 : P5);
        if (sel == 2) Cb = O0 + (size_t)g * EEc;
        else {
            bfout = true;
            Cb16 = (__nv_bfloat16*)O1 + (size_t)((sel == 0 ? 4 : 0) + g) * EEc;
        }
    } else if (MODE == 1) {
        Ab = P2; Wb = P3 + (size_t)g * EEc; bb = P4 + (8 + g) * Eq;
        Cb = O1 + (size_t)g * BSEc;
    } else {
        Ab = P0 + (size_t)z * BTEc;
        Wb = P1 + (size_t)z * EEc;
        bb = P2 + z * Eq;
        Cb = O0; cmap = true;
    }

    const int m0 = blockIdx.y * 128;
    const int n0 = blockIdx.x * 128;
    const int tid  = threadIdx.x;
    const int wid  = tid >> 5;
    const int lane = tid & 31;
    const int gid  = lane >> 2;
    const int t4   = lane & 3;
    const int wm   = (wid & 1) * 64;
    const int wn   = (wid >> 1) * 64;

    float acc[4][8][4];
    #pragma unroll
    for (int a = 0; a < 4; a++)
        #pragma unroll
        for (int b = 0; b < 8; b++)
            #pragma unroll
            for (int c = 0; c < 4; c++) acc[a][b][c] = 0.f;

    float4 pa[4], pw[4];

    auto loadA = [&](int k0) {
        #pragma unroll
        for (int p = 0; p < 4; p++) {
            int idx = tid + p * 128;
            int row = m0 + (idx >> 2);
            int q = (idx & 3) * 4;
            pa[p] = *(const float4*)&Ab[(size_t)row * Eq + k0 + q];
        }
    };
    auto loadW = [&](int k0) {
        if (MODE != 0) {
            #pragma unroll
            for (int p = 0; p < 4; p++) {
                int idx = tid + p * 128;
                int row = n0 + (idx >> 2);
                int q = (idx & 3) * 4;
                pw[p] = *(const float4*)&Wb[(size_t)row * Eq + k0 + q];
            }
        } else {
            #pragma unroll
            for (int p = 0; p < 4; p++) {
                int idx = tid + p * 128;
                int e  = idx >> 5;
                int jq = (idx & 31) * 4;
                pw[p] = *(const float4*)&Wb[(size_t)(k0 + e) * Eq + n0 + jq];
            }
        }
    };
    auto storeT = [&](int buf) {
        #pragma unroll
        for (int p = 0; p < 4; p++) {
            int idx = tid + p * 128;
            int row = idx >> 2;
            int q = (idx & 3) * 4;
            *(float4*)&As[buf][row * GS + q] = f2tf32_4(pa[p]);
        }
        if (MODE != 0) {
            #pragma unroll
            for (int p = 0; p < 4; p++) {
                int idx = tid + p * 128;
                int row = idx >> 2;
                int q = (idx & 3) * 4;
                *(float4*)&Ws[buf][row * GS + q] = f2tf32_4(pw[p]);
            }
        } else {
            #pragma unroll
            for (int p = 0; p < 4; p++) {
                int idx = tid + p * 128;
                int e  = idx >> 5;
                int jq = (idx & 31) * 4;
                *(float4*)&Ws[buf][e * WKN + jq] = f2tf32_4(pw[p]);
            }
        }
    };
    auto compute = [&](int buf) {
        #pragma unroll
        for (int kk = 0; kk < 2; kk++) {
            float afr[4][4];
            #pragma unroll
            for (int mt = 0; mt < 4; mt++) {
                int r = wm + mt * 16 + gid;
                int c = kk * 8 + t4;
                afr[mt][0] = As[buf][r * GS + c];
                afr[mt][1] = As[buf][(r + 8) * GS + c];
                afr[mt][2] = As[buf][r * GS + c + 4];
                afr[mt][3] = As[buf][(r + 8) * GS + c + 4];
            }
            float bfr[8][2];
            #pragma unroll
            for (int nt = 0; nt < 8; nt++) {
                int r = wn + nt * 8 + gid;
                int c = kk * 8 + t4;
                if (MODE == 0) {
                    bfr[nt][0] = Ws[buf][c * WKN + r];
                    bfr[nt][1] = Ws[buf][(c + 4) * WKN + r];
                } else {
                    bfr[nt][0] = Ws[buf][r * GS + c];
                    bfr[nt][1] = Ws[buf][r * GS + c + 4];
                }
            }
            #pragma unroll
            for (int mt = 0; mt < 4; mt++)
                #pragma unroll
                for (int nt = 0; nt < 8; nt++)
                    mma_tf32(acc[mt][nt], afr[mt], bfr[nt]);
        }
    };

    loadA(0); loadW(0);
    storeT(0);
    __syncthreads();

    int buf = 0;
    const int NCH = Eq / 16;   // 48
    for (int c = 0; c < NCH; c++) {
        if (c + 1 < NCH) { loadA((c + 1) * 16); loadW((c + 1) * 16); }
        compute(buf);
        if (c + 1 < NCH) storeT(1 - buf);
        __syncthreads();
        buf ^= 1;
    }

    #pragma unroll
    for (int mt = 0; mt < 4; mt++) {
        int m  = m0 + wm + mt * 16 + gid;
        int m2 = m + 8;
        size_t r0, r1;
        if (cmap) {
            r0 = (size_t)(m  >> 9) * Sq + (size_t)(m  & 511) * Gq + g;
            r1 = (size_t)(m2 >> 9) * Sq + (size_t)(m2 & 511) * Gq + g;
        } else { r0 = (size_t)m; r1 = (size_t)m2; }
        #pragma unroll
        for (int nt = 0; nt < 8; nt++) {
            int n = n0 + wn + nt * 8 + 2 * t4;
            float b0 = 0.f, b1 = 0.f;
            if (bb) { b0 = bb[n]; b1 = bb[n + 1]; }
            if (bfout) {
                *(uint32_t*)&Cb16[r0 * Eq + n] = packbf(acc[mt][nt][0] + b0, acc[mt][nt][1] + b1);
                *(uint32_t*)&Cb16[r1 * Eq + n] = packbf(acc[mt][nt][2] + b0, acc[mt][nt][3] + b1);
            } else {
                *(float2*)&Cb[r0 * Eq + n] = make_float2(acc[mt][nt][0] + b0, acc[mt][nt][1] + b1);
                *(float2*)&Cb[r1 * Eq + n] = make_float2(acc[mt][nt][2] + b0, acc[mt][nt][3] + b1);
            }
        }
    }
}

// ---------------------------------------------------------------------------
// bf16 GEMM for ki + qi projections (double-buffered, one sync per chunk).
// z 0..3: ki[g] = key @ wcb[g].T + bc_k[g]    (y full)
// z 4..7: qi[g] = gather_g(query) @ wcb[4+g].T + bc_q[g]   (y < 8, amap)
// ---------------------------------------------------------------------------
#define BS2 24

__global__ __launch_bounds__(128)
void gemm_bf16_kq(const float* __restrict__ key_, const float* __restrict__ query,
                  const __nv_bfloat16* __restrict__ W,      // wcb [8][768][768]
                  const float* __restrict__ bc,             // full bias table
                  __nv_bfloat16* __restrict__ kib,
                  __nv_bfloat16* __restrict__ qib)
{
    __shared__ __nv_bfloat16 As2[2][128 * BS2];
    __shared__ __nv_bfloat16 Ws2[2][128 * BS2];

    const int z = blockIdx.z;
    const int sel = z >> 2, g = z & 3;
    if (sel == 1 && blockIdx.y >= 8) return;

    const float* Ab = (sel == 0) ? key_ : query;
    const __nv_bfloat16* Wb = W + (size_t)((sel == 0 ? 0 : 4) + g) * EEc;
    const float* bb = bc + ((sel == 0 ? 4 : 0) + g) * Eq;
    __nv_bfloat16* Cb = (sel == 0) ? (kib + (size_t)g * BSEc)
                                   : (qib + (size_t)g * BTEc);
    const bool amap = (sel == 1);

    const int m0 = blockIdx.y * 128;
    const int n0 = blockIdx.x * 128;
    const int tid  = threadIdx.x;
    const int wid  = tid >> 5;
    const int lane = tid & 31;
    const int gid  = lane >> 2;
    const int t4   = lane & 3;
    const int wm   = (wid & 1) * 64;
    const int wn   = (wid >> 1) * 64;

    float acc[4][8][4];
    #pragma unroll
    for (int a = 0; a < 4; a++)
        #pragma unroll
        for (int b = 0; b < 8; b++)
            #pragma unroll
            for (int c = 0; c < 4; c++) acc[a][b][c] = 0.f;

    float4 pa[4];
    uint2  pw[4];

    auto loadA = [&](int k0) {
        #pragma unroll
        for (int p = 0; p < 4; p++) {
            int idx = tid + p * 128;
            int row = m0 + (idx >> 2);
            int q4 = (idx & 3) * 4;
            size_t gr;
            if (amap) gr = (size_t)(row >> 9) * Sq + (size_t)(row & 511) * Gq + g;
            else      gr = (size_t)row;
            pa[p] = *(const float4*)&Ab[gr * Eq + k0 + q4];
        }
    };
    auto loadW = [&](int k0) {
        #pragma unroll
        for (int p = 0; p < 4; p++) {
            int idx = tid + p * 128;
            int row = n0 + (idx >> 2);
            int q4 = (idx & 3) * 4;
            pw[p] = *(const uint2*)&Wb[(size_t)row * Eq + k0 + q4];
        }
    };
    auto storeT = [&](int buf) {
        #pragma unroll
        for (int p = 0; p < 4; p++) {
            int idx = tid + p * 128;
            int row = idx >> 2;
            int q4 = (idx & 3) * 4;
            uint2 v;
            v.x = packbf(pa[p].x, pa[p].y);
            v.y = packbf(pa[p].z, pa[p].w);
            *(uint2*)&As2[buf][row * BS2 + q4] = v;
            *(uint2*)&Ws2[buf][row * BS2 + q4] = pw[p];
        }
    };
    auto compute = [&](int buf) {
        uint32_t afr[4][4];
        #pragma unroll
        for (int mt = 0; mt < 4; mt++) {
            int r = wm + mt * 16 + gid;
            int c = 2 * t4;
            afr[mt][0] = *(const uint32_t*)&As2[buf][r * BS2 + c];
            afr[mt][1] = *(const uint32_t*)&As2[buf][(r + 8) * BS2 + c];
            afr[mt][2] = *(const uint32_t*)&As2[buf][r * BS2 + c + 8];
            afr[mt][3] = *(const uint32_t*)&As2[buf][(r + 8) * BS2 + c + 8];
        }
        uint32_t bfr[8][2];
        #pragma unroll
        for (int nt = 0; nt < 8; nt++) {
            int r = wn + nt * 8 + gid;
            int c = 2 * t4;
            bfr[nt][0] = *(const uint32_t*)&Ws2[buf][r * BS2 + c];
            bfr[nt][1] = *(const uint32_t*)&Ws2[buf][r * BS2 + c + 8];
        }
        #pragma unroll
        for (int mt = 0; mt < 4; mt++)
            #pragma unroll
            for (int nt = 0; nt < 8; nt++)
                mma_bf16(acc[mt][nt], afr[mt], bfr[nt]);
    };

    loadA(0); loadW(0);
    storeT(0);
    __syncthreads();

    int buf = 0;
    const int NCH = Eq / 16;
    for (int c = 0; c < NCH; c++) {
        if (c + 1 < NCH) { loadA((c + 1) * 16); loadW((c + 1) * 16); }
        compute(buf);
        if (c + 1 < NCH) storeT(1 - buf);
        __syncthreads();
        buf ^= 1;
    }

    #pragma unroll
    for (int mt = 0; mt < 4; mt++) {
        int m  = m0 + wm + mt * 16 + gid;
        int m2 = m + 8;
        #pragma unroll
        for (int nt = 0; nt < 8; nt++) {
            int n = n0 + wn + nt * 8 + 2 * t4;
            float b0 = bb[n], b1 = bb[n + 1];
            *(uint32_t*)&Cb[(size_t)m  * Eq + n] = packbf(acc[mt][nt][0] + b0, acc[mt][nt][1] + b1);
            *(uint32_t*)&Cb[(size_t)m2 * Eq + n] = packbf(acc[mt][nt][2] + b0, acc[mt][nt][3] + b1);
        }
    }
}

// ---------------------------------------------------------------------------
// Fused bias compose (unchanged)
// ---------------------------------------------------------------------------
__global__ void biascomp_all(const float* __restrict__ Wq_in, const float* __restrict__ Wk_in,
                             const float* __restrict__ Wv_in,
                             const float* __restrict__ bqg, const float* __restrict__ bk,
                             const float* __restrict__ bv,
                             const float* __restrict__ bq_in, const float* __restrict__ bk_in,
                             const float* __restrict__ bv_in,
                             float* __restrict__ bc)
{
    int y = blockIdx.y;
    int sel = y >> 2, g = y & 3;
    const float* Win = (sel == 0 ? Wq_in : sel == 1 ? Wk_in : Wv_in) + (size_t)g * EEc;
    const float* bo  = (sel == 0 ? bqg : sel == 1 ? bk : bv);
    const float* bi  = (sel == 0 ? bq_in : sel == 1 ? bk_in : bv_in) + g * Eq;
    int f = blockIdx.x * 8 + (threadIdx.x >> 5);
    int lane = threadIdx.x & 31;
    const float* wr = Win + (size_t)f * Eq;
    float s = 0.f;
    for (int j = lane * 4; j < Eq; j += 128) {
        float4 w = *(const float4*)&wr[j];
        float4 b = *(const float4*)&bo[j];
        s += w.x*b.x + w.y*b.y + w.z*b.z + w.w*b.w;
    }
    #pragma unroll
    for (int o = 16; o; o >>= 1) s += __shfl_xor_sync(0xffffffffu, s, o);
    if (lane == 0) bc[(size_t)y * Eq + f] = s + bi[f];
}

// ---------------------------------------------------------------------------
// Flash attention — EXACT round-8 version (proven 206 us).
// ---------------------------------------------------------------------------
#define KSB 72
#define VSF 72
#define QSB 72
#define PSF 68

__global__ __launch_bounds__(128)
void flash_mixed_kernel(const __nv_bfloat16* __restrict__ qi,
                        const __nv_bfloat16* __restrict__ ki,
                        const float* __restrict__ vi,
                        float* __restrict__ ctx)
{
    __shared__ __align__(16) __nv_bfloat16 Ks[64 * KSB];
    __shared__ __align__(16) float         Vs[64 * VSF];
    __shared__ __align__(16) unsigned char QPbuf[64 * PSF * 4];
    __nv_bfloat16* Qs = (__nv_bfloat16*)QPbuf;
    float*         Ps = (float*)QPbuf;

    const int zz = blockIdx.z;
    const int h  = blockIdx.y;
    const int t0 = blockIdx.x * 64;
    const size_t qbase = ((size_t)zz * Tq + t0) * Eq + (size_t)h * Dq;
    const size_t kbase = (size_t)zz * Sq * Eq + (size_t)h * Dq;

    const int tid  = threadIdx.x;
    const int wid  = tid >> 5;
    const int lane = tid & 31;
    const int gid  = lane >> 2;
    const int t4   = lane & 3;
    const int wrow = wid * 16;

    #pragma unroll
    for (int i = 0; i < 4; i++) {
        int idx = tid + i * 128;
        int row = idx >> 3;
        int c8  = idx & 7;
        uint4 v = *(const uint4*)&qi[qbase + (size_t)row * Eq + c8 * 8];
        *(uint2*)&Qs[row * QSB + c8 * 8]     = make_uint2(v.x, v.y);
        *(uint2*)&Qs[row * QSB + c8 * 8 + 4] = make_uint2(v.z, v.w);
    }
    __syncthreads();

    uint32_t Aq[4][4];
    #pragma unroll
    for (int kk = 0; kk < 4; kk++) {
        int r = wrow + gid;
        int c = kk * 16 + 2 * t4;
        Aq[kk][0] = *(const uint32_t*)&Qs[r * QSB + c];
        Aq[kk][1] = *(const uint32_t*)&Qs[(r + 8) * QSB + c];
        Aq[kk][2] = *(const uint32_t*)&Qs[r * QSB + c + 8];
        Aq[kk][3] = *(const uint32_t*)&Qs[(r + 8) * QSB + c + 8];
    }

    float out[8][4];
    #pragma unroll
    for (int j = 0; j < 8; j++)
        #pragma unroll
        for (int c = 0; c < 4; c++) out[j][c] = 0.f;
    float mrow[2] = {-1e30f, -1e30f};
    float lrow[2] = {0.f, 0.f};
    const float kappa = 0.125f * 1.44269504088896340736f;

    for (int s0 = 0; s0 < Sq; s0 += 64) {
        __syncthreads();
        #pragma unroll
        for (int i = 0; i < 4; i++) {
            int idx = tid + i * 128;
            int row = idx >> 3;
            int c8  = idx & 7;
            uint4 v = *(const uint4*)&ki[kbase + (size_t)(s0 + row) * Eq + c8 * 8];
            *(uint2*)&Ks[row * KSB + c8 * 8]     = make_uint2(v.x, v.y);
            *(uint2*)&Ks[row * KSB + c8 * 8 + 4] = make_uint2(v.z, v.w);
        }
        #pragma unroll
        for (int i = 0; i < 8; i++) {
            int idx = tid + i * 128;
            int row = idx >> 4;
            int c4  = idx & 15;
            float4 vv = *(const float4*)&vi[kbase + (size_t)(s0 + row) * Eq + c4 * 4];
            *(float4*)&Vs[row * VSF + c4 * 4] = f2tf32_4(vv);
        }
        __syncthreads();

        float sc[8][4];
        #pragma unroll
        for (int j = 0; j < 8; j++)
            #pragma unroll
            for (int c = 0; c < 4; c++) sc[j][c] = 0.f;
        #pragma unroll
        for (int kk = 0; kk < 4; kk++) {
            #pragma unroll
            for (int j = 0; j < 8; j++) {
                const __nv_bfloat16* kr = &Ks[(j * 8 + gid) * KSB + kk * 16 + 2 * t4];
                uint32_t b[2];
                b[0] = *(const uint32_t*)kr;
                b[1] = *(const uint32_t*)(kr + 8);
                mma_bf16(sc[j], Aq[kk], b);
            }
        }

        #pragma unroll
        for (int j = 0; j < 8; j++)
            #pragma unroll
            for (int c = 0; c < 4; c++) sc[j][c] *= kappa;

        #pragma unroll
        for (int r = 0; r < 2; r++) {
            float mx = -1e30f;
            #pragma unroll
            for (int j = 0; j < 8; j++)
                mx = fmaxf(mx, fmaxf(sc[j][2*r], sc[j][2*r + 1]));
            mx = fmaxf(mx, __shfl_xor_sync(0xffffffffu, mx, 1));
            mx = fmaxf(mx, __shfl_xor_sync(0xffffffffu, mx, 2));
            float mn = fmaxf(mrow[r], mx);
            float corr = exp2f(mrow[r] - mn);
            mrow[r] = mn;
            float rs = 0.f;
            #pragma unroll
            for (int j = 0; j < 8; j++) {
                float p0 = exp2f(sc[j][2*r]     - mn);
                float p1 = exp2f(sc[j][2*r + 1] - mn);
                sc[j][2*r]     = p0;
                sc[j][2*r + 1] = p1;
                rs += p0 + p1;
            }
            rs += __shfl_xor_sync(0xffffffffu, rs, 1);
            rs += __shfl_xor_sync(0xffffffffu, rs, 2);
            lrow[r] = lrow[r] * corr + rs;
            #pragma unroll
            for (int j = 0; j < 8; j++) {
                out[j][2*r]     *= corr;
                out[j][2*r + 1] *= corr;
            }
        }

        #pragma unroll
        for (int j = 0; j < 8; j++) {
            int col = j * 8 + 2 * t4;
            *(float2*)&Ps[(wrow + gid) * PSF + col] =
                make_float2(f2tf32(sc[j][0]), f2tf32(sc[j][1]));
            *(float2*)&Ps[(wrow + gid + 8) * PSF + col] =
                make_float2(f2tf32(sc[j][2]), f2tf32(sc[j][3]));
        }
        __syncwarp();

        #pragma unroll
        for (int kk = 0; kk < 8; kk++) {
            float afr[4];
            int r = wrow + gid;
            int c = kk * 8 + t4;
            afr[0] = Ps[r * PSF + c];
            afr[1] = Ps[(r + 8) * PSF + c];
            afr[2] = Ps[r * PSF + c + 4];
            afr[3] = Ps[(r + 8) * PSF + c + 4];
            #pragma unroll
            for (int j = 0; j < 8; j++) {
                float bfr[2];
                int key = kk * 8 + t4;
                int d   = j * 8 + gid;
                bfr[0] = Vs[key * VSF + d];
                bfr[1] = Vs[(key + 4) * VSF + d];
                mma_tf32(out[j], afr, bfr);
            }
        }
    }

    float inv0 = 1.0f / lrow[0];
    float inv1 = 1.0f / lrow[1];
    int r0 = wrow + gid;
    #pragma unroll
    for (int j = 0; j < 8; j++) {
        int col = j * 8 + 2 * t4;
        *(float2*)&ctx[qbase + (size_t)r0 * Eq + col] =
            make_float2(out[j][0] * inv0, out[j][1] * inv0);
        *(float2*)&ctx[qbase + (size_t)(r0 + 8) * Eq + col] =
            make_float2(out[j][2] * inv1, out[j][3] * inv1);
    }
}

// ---------------------------------------------------------------------------
// Launch
// ---------------------------------------------------------------------------
extern "C" void kernel_launch(void* const* d_in, const int* in_sizes, int n_in,
                              void* d_out, int out_size)
{
    const float* query = (const float*)d_in[0];
    const float* key_  = (const float*)d_in[1];
    const float* value = (const float*)d_in[2];
    const float* Wqg   = (const float*)d_in[3];
    const float* bqg   = (const float*)d_in[4];
    const float* Wk    = (const float*)d_in[5];
    const float* bk    = (const float*)d_in[6];
    const float* Wv    = (const float*)d_in[7];
    const float* bv    = (const float*)d_in[8];
    const float* Wq_in = (const float*)d_in[9];
    const float* bq_in = (const float*)d_in[10];
    const float* Wk_in = (const float*)d_in[11];
    const float* bk_in = (const float*)d_in[12];
    const float* Wv_in = (const float*)d_in[13];
    const float* bv_in = (const float*)d_in[14];
    const float* Wout  = (const float*)d_in[15];
    const float* bout  = (const float*)d_in[16];
    float* out = (float*)d_out;

    float *wc, *bc, *viP, *ctx;
    __nv_bfloat16 *wcbP, *qibP, *kibP;
    cudaGetSymbolAddress((void**)&wc,   g_wc);
    cudaGetSymbolAddress((void**)&wcbP, g_wcb);
    cudaGetSymbolAddress((void**)&bc,   g_bc);
    cudaGetSymbolAddress((void**)&qibP, g_qib);
    cudaGetSymbolAddress((void**)&kibP, g_kib);
    cudaGetSymbolAddress((void**)&viP,  g_vi);
    cudaGetSymbolAddress((void**)&ctx,  g_ctx);

    // 1) Fused bias compose
    biascomp_all<<<dim3(Eq / 8, 12), 256>>>(Wq_in, Wk_in, Wv_in,
                                            bqg, bk, bv,
                                            bq_in, bk_in, bv_in, bc);

    // 2) Fused weight compose: q->bf16(slot 4+g), k->bf16(slot g), v->f32
    gemm_k<0><<<dim3(Eq / 128, Eq / 128, 12), 128>>>(
        Wq_in, Wk_in, Wv_in, Wqg, Wk, Wv, wc, (float*)wcbP, nullptr);

    // 3a) ki + qi projections (bf16 GEMM, one launch)
    gemm_bf16_kq<<<dim3(Eq / 128, (Bq * Sq) / 128, 8), 128>>>(
        key_, query, wcbP, bc, kibP, qibP);

    // 3b) vi projection (tf32 GEMM)
    gemm_k<1><<<dim3(Eq / 128, (Bq * Sq) / 128, 4), 128>>>(
        nullptr, nullptr, value, wc, bc, nullptr,
        nullptr, viP, nullptr);

    // 4) Attention (R8-exact mixed flash)
    flash_mixed_kernel<<<dim3(Tq / 64, Hq, Bq * Gq), 128>>>(qibP, kibP, viP, ctx);

    // 5) Output projection + scatter
    gemm_k<2><<<dim3(Eq / 128, (Bq * Tq) / 128, Gq), 128>>>(
        ctx, Wout, bout, nullptr, nullptr, nullptr, out, nullptr, nullptr);
}

// round 14
// speedup vs baseline: 1.0553x; 1.0553x over previous
#include <cuda_runtime.h>
#include <cuda_bf16.h>
#include <cstdint>

// Problem constants
#define Bq 2
#define Sq 2048
#define Eq 768
#define Hq 12
#define Gq 4
#define Dq 64
#define Tq 512   // Sq / Gq

#define EEc  ((size_t)Eq * Eq)
#define BTEc ((size_t)Bq * Tq * Eq)
#define BSEc ((size_t)Bq * Sq * Eq)

// ---------------------------------------------------------------------------
// Scratch (device globals)
// ---------------------------------------------------------------------------
__device__ float g_wc[4 * EEc];                        // composed f32: v g0..3
__device__ __nv_bfloat16 g_wcb[8 * EEc];               // composed bf16: [k g0..3 | q g0..3]
__device__ float g_bc[12 * Eq];                        // composed biases [q|k|v]
__device__ __nv_bfloat16 g_qib[(size_t)Gq*Bq*Tq*Eq];   // qi bf16
__device__ __nv_bfloat16 g_kib[(size_t)Gq*Bq*Sq*Eq];   // ki bf16
__device__ float g_vi [(size_t)Gq*Bq*Sq*Eq];           // vi fp32
__device__ float g_ctx[(size_t)Gq*Bq*Tq*Eq];           // ctx fp32

// ---------------------------------------------------------------------------
// helpers
// ---------------------------------------------------------------------------
__device__ __forceinline__ float f2tf32(float x) {
    uint32_t r;
    asm("cvt.rna.tf32.f32 %0, %1;" : "=r"(r) : "f"(x));
    return __uint_as_float(r);
}
__device__ __forceinline__ float4 f2tf32_4(float4 v) {
    return make_float4(f2tf32(v.x), f2tf32(v.y), f2tf32(v.z), f2tf32(v.w));
}
__device__ __forceinline__ void mma_tf32(float (&d)[4], const float a[4], const float b[2]) {
    asm volatile(
        "mma.sync.aligned.m16n8k8.row.col.f32.tf32.tf32.f32 "
        "{%0,%1,%2,%3}, {%4,%5,%6,%7}, {%8,%9}, {%0,%1,%2,%3};\n"
        : "+f"(d[0]), "+f"(d[1]), "+f"(d[2]), "+f"(d[3])
        : "r"(__float_as_uint(a[0])), "r"(__float_as_uint(a[1])),
          "r"(__float_as_uint(a[2])), "r"(__float_as_uint(a[3])),
          "r"(__float_as_uint(b[0])), "r"(__float_as_uint(b[1])));
}
__device__ __forceinline__ void mma_bf16(float (&d)[4], const uint32_t a[4], const uint32_t b[2]) {
    asm volatile(
        "mma.sync.aligned.m16n8k16.row.col.f32.bf16.bf16.f32 "
        "{%0,%1,%2,%3}, {%4,%5,%6,%7}, {%8,%9}, {%0,%1,%2,%3};\n"
        : "+f"(d[0]), "+f"(d[1]), "+f"(d[2]), "+f"(d[3])
        : "r"(a[0]), "r"(a[1]), "r"(a[2]), "r"(a[3]),
          "r"(b[0]), "r"(b[1]));
}
__device__ __forceinline__ uint32_t packbf(float lo, float hi) {
    uint32_t r;
    asm("cvt.rn.bf16x2.f32 %0, %1, %2;" : "=r"(r) : "f"(hi), "f"(lo));
    return r;
}

// ---------------------------------------------------------------------------
// tf32 GEMM (compose + out), 128 thr / 4 warps, 128x128 tile, warp 64x64,
// double-buffered smem, one sync per chunk.
// MODE 0 (compose, z 0..11): sel0 wcb_q(bf16, slot 4+g), sel1 wcb_k(bf16, slot g),
//                            sel2 wc_v(f32). W read [k][n], stride WKN=136
//                            (banks 8*t4+gid — conflict-free; 132 was 2-way).
// MODE 2 (out, z 0..3): out = scatter_g(ctx[z] @ Wout[z].T + bout[z])
// ---------------------------------------------------------------------------
#define GS 20
#define WKN 136

template<int MODE>
__global__ __launch_bounds__(128)
void gemm_k(const float* __restrict__ P0, const float* __restrict__ P1,
            const float* __restrict__ P2, const float* __restrict__ P3,
            const float* __restrict__ P4, const float* __restrict__ P5,
            float* __restrict__ O0, float* __restrict__ O1, float* __restrict__ O2)
{
    __shared__ float As[2][128 * GS];
    __shared__ float Ws[2][128 * GS];   // MODE0 uses 16*136=2176 <= 2560 per buf

    const int z = blockIdx.z;
    const int sel = z >> 2, g = z & 3;

    const float* Ab; const float* Wb; const float* bb = nullptr;
    float* Cb = nullptr; __nv_bfloat16* Cb16 = nullptr;
    bool cmap = false, bfout = false;
    if (MODE == 0) {
        Ab = (sel == 0 ? P0 : sel == 1 ? P1 : P2) + (size_t)g * EEc;
        Wb = (sel == 0 ? P3 : sel == 1 ? P4 : P5);
        if (sel == 2) Cb = O0 + (size_t)g * EEc;
        else {
            bfout = true;
            Cb16 = (__nv_bfloat16*)O1 + (size_t)((sel == 0 ? 4 : 0) + g) * EEc;
        }
    } else {
        Ab = P0 + (size_t)z * BTEc;
        Wb = P1 + (size_t)z * EEc;
        bb = P2 + z * Eq;
        Cb = O0; cmap = true;
    }

    const int m0 = blockIdx.y * 128;
    const int n0 = blockIdx.x * 128;
    const int tid  = threadIdx.x;
    const int wid  = tid >> 5;
    const int lane = tid & 31;
    const int gid  = lane >> 2;
    const int t4   = lane & 3;
    const int wm   = (wid & 1) * 64;
    const int wn   = (wid >> 1) * 64;

    float acc[4][8][4];
    #pragma unroll
    for (int a = 0; a < 4; a++)
        #pragma unroll
        for (int b = 0; b < 8; b++)
            #pragma unroll
            for (int c = 0; c < 4; c++) acc[a][b][c] = 0.f;

    float4 pa[4], pw[4];

    auto loadA = [&](int k0) {
        #pragma unroll
        for (int p = 0; p < 4; p++) {
            int idx = tid + p * 128;
            int row = m0 + (idx >> 2);
            int q = (idx & 3) * 4;
            pa[p] = *(const float4*)&Ab[(size_t)row * Eq + k0 + q];
        }
    };
    auto loadW = [&](int k0) {
        if (MODE != 0) {
            #pragma unroll
            for (int p = 0; p < 4; p++) {
                int idx = tid + p * 128;
                int row = n0 + (idx >> 2);
                int q = (idx & 3) * 4;
                pw[p] = *(const float4*)&Wb[(size_t)row * Eq + k0 + q];
            }
        } else {
            #pragma unroll
            for (int p = 0; p < 4; p++) {
                int idx = tid + p * 128;
                int e  = idx >> 5;
                int jq = (idx & 31) * 4;
                pw[p] = *(const float4*)&Wb[(size_t)(k0 + e) * Eq + n0 + jq];
            }
        }
    };
    auto storeT = [&](int buf) {
        #pragma unroll
        for (int p = 0; p < 4; p++) {
            int idx = tid + p * 128;
            int row = idx >> 2;
            int q = (idx & 3) * 4;
            *(float4*)&As[buf][row * GS + q] = f2tf32_4(pa[p]);
        }
        if (MODE != 0) {
            #pragma unroll
            for (int p = 0; p < 4; p++) {
                int idx = tid + p * 128;
                int row = idx >> 2;
                int q = (idx & 3) * 4;
                *(float4*)&Ws[buf][row * GS + q] = f2tf32_4(pw[p]);
            }
        } else {
            #pragma unroll
            for (int p = 0; p < 4; p++) {
                int idx = tid + p * 128;
                int e  = idx >> 5;
                int jq = (idx & 31) * 4;
                *(float4*)&Ws[buf][e * WKN + jq] = f2tf32_4(pw[p]);
            }
        }
    };
    auto compute = [&](int buf) {
        #pragma unroll
        for (int kk = 0; kk < 2; kk++) {
            float afr[4][4];
            #pragma unroll
            for (int mt = 0; mt < 4; mt++) {
                int r = wm + mt * 16 + gid;
                int c = kk * 8 + t4;
                afr[mt][0] = As[buf][r * GS + c];
                afr[mt][1] = As[buf][(r + 8) * GS + c];
                afr[mt][2] = As[buf][r * GS + c + 4];
                afr[mt][3] = As[buf][(r + 8) * GS + c + 4];
            }
            float bfr[8][2];
            #pragma unroll
            for (int nt = 0; nt < 8; nt++) {
                int r = wn + nt * 8 + gid;
                int c = kk * 8 + t4;
                if (MODE == 0) {
                    bfr[nt][0] = Ws[buf][c * WKN + r];
                    bfr[nt][1] = Ws[buf][(c + 4) * WKN + r];
                } else {
                    bfr[nt][0] = Ws[buf][r * GS + c];
                    bfr[nt][1] = Ws[buf][r * GS + c + 4];
                }
            }
            #pragma unroll
            for (int mt = 0; mt < 4; mt++)
                #pragma unroll
                for (int nt = 0; nt < 8; nt++)
                    mma_tf32(acc[mt][nt], afr[mt], bfr[nt]);
        }
    };

    loadA(0); loadW(0);
    storeT(0);
    __syncthreads();

    int buf = 0;
    const int NCH = Eq / 16;
    for (int c = 0; c < NCH; c++) {
        if (c + 1 < NCH) { loadA((c + 1) * 16); loadW((c + 1) * 16); }
        compute(buf);
        if (c + 1 < NCH) storeT(1 - buf);
        __syncthreads();
        buf ^= 1;
    }

    #pragma unroll
    for (int mt = 0; mt < 4; mt++) {
        int m  = m0 + wm + mt * 16 + gid;
        int m2 = m + 8;
        size_t r0, r1;
        if (cmap) {
            r0 = (size_t)(m  >> 9) * Sq + (size_t)(m  & 511) * Gq + g;
            r1 = (size_t)(m2 >> 9) * Sq + (size_t)(m2 & 511) * Gq + g;
        } else { r0 = (size_t)m; r1 = (size_t)m2; }
        #pragma unroll
        for (int nt = 0; nt < 8; nt++) {
            int n = n0 + wn + nt * 8 + 2 * t4;
            float b0 = 0.f, b1 = 0.f;
            if (bb) { b0 = bb[n]; b1 = bb[n + 1]; }
            if (bfout) {
                *(uint32_t*)&Cb16[r0 * Eq + n] = packbf(acc[mt][nt][0] + b0, acc[mt][nt][1] + b1);
                *(uint32_t*)&Cb16[r1 * Eq + n] = packbf(acc[mt][nt][2] + b0, acc[mt][nt][3] + b1);
            } else {
                *(float2*)&Cb[r0 * Eq + n] = make_float2(acc[mt][nt][0] + b0, acc[mt][nt][1] + b1);
                *(float2*)&Cb[r1 * Eq + n] = make_float2(acc[mt][nt][2] + b0, acc[mt][nt][3] + b1);
            }
        }
    }
}

// ---------------------------------------------------------------------------
// MERGED projection kernel — one launch, z 0..11:
//   z 0..3 : ki[g] = key @ wcb[g].T + bc_k       (bf16 MMA, bf16 out)
//   z 4..7 : qi[g] = gather_g(query) @ wcb[4+g]  (bf16 MMA, bf16 out, y<8)
//   z 8..11: vi[g] = value @ wc_v[g] + bc_v      (tf32 MMA, f32 out)
// bf16 blocks (tensor-heavy) and tf32 blocks (latency-heavy) co-schedule on
// the same SMs, overlapping each other's stalls. Smem union: tf32 uses full
// 2x10KB pairs; bf16 path reinterprets the first 6144B of each buffer.
// ---------------------------------------------------------------------------
#define BS2 24

__global__ __launch_bounds__(128)
void gemm_proj(const float* __restrict__ key_, const float* __restrict__ query,
               const float* __restrict__ value,
               const __nv_bfloat16* __restrict__ Wcb,   // [8][768][768] bf16
               const float* __restrict__ Wcv,           // [4][768][768] f32
               const float* __restrict__ bc,
               __nv_bfloat16* __restrict__ kib,
               __nv_bfloat16* __restrict__ qib,
               float* __restrict__ vif)
{
    __shared__ __align__(16) float smA[2][128 * GS];   // 20 KB
    __shared__ __align__(16) float smW[2][128 * GS];   // 20 KB

    const int z = blockIdx.z;
    const int sel = z >> 2, g = z & 3;
    const int NCH = Eq / 16;

    const int m0 = blockIdx.y * 128;
    const int n0 = blockIdx.x * 128;
    const int tid  = threadIdx.x;
    const int wid  = tid >> 5;
    const int lane = tid & 31;
    const int gid  = lane >> 2;
    const int t4   = lane & 3;
    const int wm   = (wid & 1) * 64;
    const int wn   = (wid >> 1) * 64;

    if (sel < 2) {
        // ================= bf16 path (ki / qi) =================
        if (sel == 1 && blockIdx.y >= 8) return;
        const float* Ab = (sel == 0) ? key_ : query;
        const __nv_bfloat16* Wb = Wcb + (size_t)((sel == 0 ? 0 : 4) + g) * EEc;
        const float* bb = bc + ((sel == 0 ? 4 : 0) + g) * Eq;
        __nv_bfloat16* Cb = (sel == 0) ? (kib + (size_t)g * BSEc)
                                       : (qib + (size_t)g * BTEc);
        const bool amap = (sel == 1);

        float acc[4][8][4];
        #pragma unroll
        for (int a = 0; a < 4; a++)
            #pragma unroll
            for (int b = 0; b < 8; b++)
                #pragma unroll
                for (int c = 0; c < 4; c++) acc[a][b][c] = 0.f;

        float4 pa[4];
        uint2  pw[4];

        auto loadA = [&](int k0) {
            #pragma unroll
            for (int p = 0; p < 4; p++) {
                int idx = tid + p * 128;
                int row = m0 + (idx >> 2);
                int q4 = (idx & 3) * 4;
                size_t gr;
                if (amap) gr = (size_t)(row >> 9) * Sq + (size_t)(row & 511) * Gq + g;
                else      gr = (size_t)row;
                pa[p] = *(const float4*)&Ab[gr * Eq + k0 + q4];
            }
        };
        auto loadW = [&](int k0) {
            #pragma unroll
            for (int p = 0; p < 4; p++) {
                int idx = tid + p * 128;
                int row = n0 + (idx >> 2);
                int q4 = (idx & 3) * 4;
                pw[p] = *(const uint2*)&Wb[(size_t)row * Eq + k0 + q4];
            }
        };
        auto storeT = [&](int buf) {
            __nv_bfloat16* As2 = (__nv_bfloat16*)smA[buf];
            __nv_bfloat16* Ws2 = (__nv_bfloat16*)smW[buf];
            #pragma unroll
            for (int p = 0; p < 4; p++) {
                int idx = tid + p * 128;
                int row = idx >> 2;
                int q4 = (idx & 3) * 4;
                uint2 v;
                v.x = packbf(pa[p].x, pa[p].y);
                v.y = packbf(pa[p].z, pa[p].w);
                *(uint2*)&As2[row * BS2 + q4] = v;
                *(uint2*)&Ws2[row * BS2 + q4] = pw[p];
            }
        };
        auto compute = [&](int buf) {
            const __nv_bfloat16* As2 = (const __nv_bfloat16*)smA[buf];
            const __nv_bfloat16* Ws2 = (const __nv_bfloat16*)smW[buf];
            uint32_t afr[4][4];
            #pragma unroll
            for (int mt = 0; mt < 4; mt++) {
                int r = wm + mt * 16 + gid;
                int c = 2 * t4;
                afr[mt][0] = *(const uint32_t*)&As2[r * BS2 + c];
                afr[mt][1] = *(const uint32_t*)&As2[(r + 8) * BS2 + c];
                afr[mt][2] = *(const uint32_t*)&As2[r * BS2 + c + 8];
                afr[mt][3] = *(const uint32_t*)&As2[(r + 8) * BS2 + c + 8];
            }
            uint32_t bfr[8][2];
            #pragma unroll
            for (int nt = 0; nt < 8; nt++) {
                int r = wn + nt * 8 + gid;
                int c = 2 * t4;
                bfr[nt][0] = *(const uint32_t*)&Ws2[r * BS2 + c];
                bfr[nt][1] = *(const uint32_t*)&Ws2[r * BS2 + c + 8];
            }
            #pragma unroll
            for (int mt = 0; mt < 4; mt++)
                #pragma unroll
                for (int nt = 0; nt < 8; nt++)
                    mma_bf16(acc[mt][nt], afr[mt], bfr[nt]);
        };

        loadA(0); loadW(0);
        storeT(0);
        __syncthreads();
        int buf = 0;
        for (int c = 0; c < NCH; c++) {
            if (c + 1 < NCH) { loadA((c + 1) * 16); loadW((c + 1) * 16); }
            compute(buf);
            if (c + 1 < NCH) storeT(1 - buf);
            __syncthreads();
            buf ^= 1;
        }

        #pragma unroll
        for (int mt = 0; mt < 4; mt++) {
            int m  = m0 + wm + mt * 16 + gid;
            int m2 = m + 8;
            #pragma unroll
            for (int nt = 0; nt < 8; nt++) {
                int n = n0 + wn + nt * 8 + 2 * t4;
                float b0 = bb[n], b1 = bb[n + 1];
                *(uint32_t*)&Cb[(size_t)m  * Eq + n] = packbf(acc[mt][nt][0] + b0, acc[mt][nt][1] + b1);
                *(uint32_t*)&Cb[(size_t)m2 * Eq + n] = packbf(acc[mt][nt][2] + b0, acc[mt][nt][3] + b1);
            }
        }
    } else {
        // ================= tf32 path (vi) =================
        const float* Ab = value;
        const float* Wb = Wcv + (size_t)g * EEc;
        const float* bb = bc + (8 + g) * Eq;
        float* Cb = vif + (size_t)g * BSEc;

        float acc[4][8][4];
        #pragma unroll
        for (int a = 0; a < 4; a++)
            #pragma unroll
            for (int b = 0; b < 8; b++)
                #pragma unroll
                for (int c = 0; c < 4; c++) acc[a][b][c] = 0.f;

        float4 pa[4], pw[4];

        auto loadA = [&](int k0) {
            #pragma unroll
            for (int p = 0; p < 4; p++) {
                int idx = tid + p * 128;
                int row = m0 + (idx >> 2);
                int q = (idx & 3) * 4;
                pa[p] = *(const float4*)&Ab[(size_t)row * Eq + k0 + q];
            }
        };
        auto loadW = [&](int k0) {
            #pragma unroll
            for (int p = 0; p < 4; p++) {
                int idx = tid + p * 128;
                int row = n0 + (idx >> 2);
                int q = (idx & 3) * 4;
                pw[p] = *(const float4*)&Wb[(size_t)row * Eq + k0 + q];
            }
        };
        auto storeT = [&](int buf) {
            #pragma unroll
            for (int p = 0; p < 4; p++) {
                int idx = tid + p * 128;
                int row = idx >> 2;
                int q = (idx & 3) * 4;
                *(float4*)&smA[buf][row * GS + q] = f2tf32_4(pa[p]);
                *(float4*)&smW[buf][row * GS + q] = f2tf32_4(pw[p]);
            }
        };
        auto compute = [&](int buf) {
            #pragma unroll
            for (int kk = 0; kk < 2; kk++) {
                float afr[4][4];
                #pragma unroll
                for (int mt = 0; mt < 4; mt++) {
                    int r = wm + mt * 16 + gid;
                    int c = kk * 8 + t4;
                    afr[mt][0] = smA[buf][r * GS + c];
                    afr[mt][1] = smA[buf][(r + 8) * GS + c];
                    afr[mt][2] = smA[buf][r * GS + c + 4];
                    afr[mt][3] = smA[buf][(r + 8) * GS + c + 4];
                }
                float bfr[8][2];
                #pragma unroll
                for (int nt = 0; nt < 8; nt++) {
                    int r = wn + nt * 8 + gid;
                    int c = kk * 8 + t4;
                    bfr[nt][0] = smW[buf][r * GS + c];
                    bfr[nt][1] = smW[buf][r * GS + c + 4];
                }
                #pragma unroll
                for (int mt = 0; mt < 4; mt++)
                    #pragma unroll
                    for (int nt = 0; nt < 8; nt++)
                        mma_tf32(acc[mt][nt], afr[mt], bfr[nt]);
            }
        };

        loadA(0); loadW(0);
        storeT(0);
        __syncthreads();
        int buf = 0;
        for (int c = 0; c < NCH; c++) {
            if (c + 1 < NCH) { loadA((c + 1) * 16); loadW((c + 1) * 16); }
            compute(buf);
            if (c + 1 < NCH) storeT(1 - buf);
            __syncthreads();
            buf ^= 1;
        }

        #pragma unroll
        for (int mt = 0; mt < 4; mt++) {
            int m  = m0 + wm + mt * 16 + gid;
            int m2 = m + 8;
            #pragma unroll
            for (int nt = 0; nt < 8; nt++) {
                int n = n0 + wn + nt * 8 + 2 * t4;
                float b0 = bb[n], b1 = bb[n + 1];
                *(float2*)&Cb[(size_t)m  * Eq + n] = make_float2(acc[mt][nt][0] + b0, acc[mt][nt][1] + b1);
                *(float2*)&Cb[(size_t)m2 * Eq + n] = make_float2(acc[mt][nt][2] + b0, acc[mt][nt][3] + b1);
            }
        }
    }
}

// ---------------------------------------------------------------------------
// Fused bias compose (unchanged)
// ---------------------------------------------------------------------------
__global__ void biascomp_all(const float* __restrict__ Wq_in, const float* __restrict__ Wk_in,
                             const float* __restrict__ Wv_in,
                             const float* __restrict__ bqg, const float* __restrict__ bk,
                             const float* __restrict__ bv,
                             const float* __restrict__ bq_in, const float* __restrict__ bk_in,
                             const float* __restrict__ bv_in,
                             float* __restrict__ bc)
{
    int y = blockIdx.y;
    int sel = y >> 2, g = y & 3;
    const float* Win = (sel == 0 ? Wq_in : sel == 1 ? Wk_in : Wv_in) + (size_t)g * EEc;
    const float* bo  = (sel == 0 ? bqg : sel == 1 ? bk : bv);
    const float* bi  = (sel == 0 ? bq_in : sel == 1 ? bk_in : bv_in) + g * Eq;
    int f = blockIdx.x * 8 + (threadIdx.x >> 5);
    int lane = threadIdx.x & 31;
    const float* wr = Win + (size_t)f * Eq;
    float s = 0.f;
    for (int j = lane * 4; j < Eq; j += 128) {
        float4 w = *(const float4*)&wr[j];
        float4 b = *(const float4*)&bo[j];
        s += w.x*b.x + w.y*b.y + w.z*b.z + w.w*b.w;
    }
    #pragma unroll
    for (int o = 16; o; o >>= 1) s += __shfl_xor_sync(0xffffffffu, s, o);
    if (lane == 0) bc[(size_t)y * Eq + f] = s + bi[f];
}

// ---------------------------------------------------------------------------
// Flash attention — EXACT round-8 version (proven 206 us).
// ---------------------------------------------------------------------------
#define KSB 72
#define VSF 72
#define QSB 72
#define PSF 68

__global__ __launch_bounds__(128)
void flash_mixed_kernel(const __nv_bfloat16* __restrict__ qi,
                        const __nv_bfloat16* __restrict__ ki,
                        const float* __restrict__ vi,
                        float* __restrict__ ctx)
{
    __shared__ __align__(16) __nv_bfloat16 Ks[64 * KSB];
    __shared__ __align__(16) float         Vs[64 * VSF];
    __shared__ __align__(16) unsigned char QPbuf[64 * PSF * 4];
    __nv_bfloat16* Qs = (__nv_bfloat16*)QPbuf;
    float*         Ps = (float*)QPbuf;

    const int zz = blockIdx.z;
    const int h  = blockIdx.y;
    const int t0 = blockIdx.x * 64;
    const size_t qbase = ((size_t)zz * Tq + t0) * Eq + (size_t)h * Dq;
    const size_t kbase = (size_t)zz * Sq * Eq + (size_t)h * Dq;

    const int tid  = threadIdx.x;
    const int wid  = tid >> 5;
    const int lane = tid & 31;
    const int gid  = lane >> 2;
    const int t4   = lane & 3;
    const int wrow = wid * 16;

    #pragma unroll
    for (int i = 0; i < 4; i++) {
        int idx = tid + i * 128;
        int row = idx >> 3;
        int c8  = idx & 7;
        uint4 v = *(const uint4*)&qi[qbase + (size_t)row * Eq + c8 * 8];
        *(uint2*)&Qs[row * QSB + c8 * 8]     = make_uint2(v.x, v.y);
        *(uint2*)&Qs[row * QSB + c8 * 8 + 4] = make_uint2(v.z, v.w);
    }
    __syncthreads();

    uint32_t Aq[4][4];
    #pragma unroll
    for (int kk = 0; kk < 4; kk++) {
        int r = wrow + gid;
        int c = kk * 16 + 2 * t4;
        Aq[kk][0] = *(const uint32_t*)&Qs[r * QSB + c];
        Aq[kk][1] = *(const uint32_t*)&Qs[(r + 8) * QSB + c];
        Aq[kk][2] = *(const uint32_t*)&Qs[r * QSB + c + 8];
        Aq[kk][3] = *(const uint32_t*)&Qs[(r + 8) * QSB + c + 8];
    }

    float out[8][4];
    #pragma unroll
    for (int j = 0; j < 8; j++)
        #pragma unroll
        for (int c = 0; c < 4; c++) out[j][c] = 0.f;
    float mrow[2] = {-1e30f, -1e30f};
    float lrow[2] = {0.f, 0.f};
    const float kappa = 0.125f * 1.44269504088896340736f;

    for (int s0 = 0; s0 < Sq; s0 += 64) {
        __syncthreads();
        #pragma unroll
        for (int i = 0; i < 4; i++) {
            int idx = tid + i * 128;
            int row = idx >> 3;
            int c8  = idx & 7;
            uint4 v = *(const uint4*)&ki[kbase + (size_t)(s0 + row) * Eq + c8 * 8];
            *(uint2*)&Ks[row * KSB + c8 * 8]     = make_uint2(v.x, v.y);
            *(uint2*)&Ks[row * KSB + c8 * 8 + 4] = make_uint2(v.z, v.w);
        }
        #pragma unroll
        for (int i = 0; i < 8; i++) {
            int idx = tid + i * 128;
            int row = idx >> 4;
            int c4  = idx & 15;
            float4 vv = *(const float4*)&vi[kbase + (size_t)(s0 + row) * Eq + c4 * 4];
            *(float4*)&Vs[row * VSF + c4 * 4] = f2tf32_4(vv);
        }
        __syncthreads();

        float sc[8][4];
        #pragma unroll
        for (int j = 0; j < 8; j++)
            #pragma unroll
            for (int c = 0; c < 4; c++) sc[j][c] = 0.f;
        #pragma unroll
        for (int kk = 0; kk < 4; kk++) {
            #pragma unroll
            for (int j = 0; j < 8; j++) {
                const __nv_bfloat16* kr = &Ks[(j * 8 + gid) * KSB + kk * 16 + 2 * t4];
                uint32_t b[2];
                b[0] = *(const uint32_t*)kr;
                b[1] = *(const uint32_t*)(kr + 8);
                mma_bf16(sc[j], Aq[kk], b);
            }
        }

        #pragma unroll
        for (int j = 0; j < 8; j++)
            #pragma unroll
            for (int c = 0; c < 4; c++) sc[j][c] *= kappa;

        #pragma unroll
        for (int r = 0; r < 2; r++) {
            float mx = -1e30f;
            #pragma unroll
            for (int j = 0; j < 8; j++)
                mx = fmaxf(mx, fmaxf(sc[j][2*r], sc[j][2*r + 1]));
            mx = fmaxf(mx, __shfl_xor_sync(0xffffffffu, mx, 1));
            mx = fmaxf(mx, __shfl_xor_sync(0xffffffffu, mx, 2));
            float mn = fmaxf(mrow[r], mx);
            float corr = exp2f(mrow[r] - mn);
            mrow[r] = mn;
            float rs = 0.f;
            #pragma unroll
            for (int j = 0; j < 8; j++) {
                float p0 = exp2f(sc[j][2*r]     - mn);
                float p1 = exp2f(sc[j][2*r + 1] - mn);
                sc[j][2*r]     = p0;
                sc[j][2*r + 1] = p1;
                rs += p0 + p1;
            }
            rs += __shfl_xor_sync(0xffffffffu, rs, 1);
            rs += __shfl_xor_sync(0xffffffffu, rs, 2);
            lrow[r] = lrow[r] * corr + rs;
            #pragma unroll
            for (int j = 0; j < 8; j++) {
                out[j][2*r]     *= corr;
                out[j][2*r + 1] *= corr;
            }
        }

        #pragma unroll
        for (int j = 0; j < 8; j++) {
            int col = j * 8 + 2 * t4;
            *(float2*)&Ps[(wrow + gid) * PSF + col] =
                make_float2(f2tf32(sc[j][0]), f2tf32(sc[j][1]));
            *(float2*)&Ps[(wrow + gid + 8) * PSF + col] =
                make_float2(f2tf32(sc[j][2]), f2tf32(sc[j][3]));
        }
        __syncwarp();

        #pragma unroll
        for (int kk = 0; kk < 8; kk++) {
            float afr[4];
            int r = wrow + gid;
            int c = kk * 8 + t4;
            afr[0] = Ps[r * PSF + c];
            afr[1] = Ps[(r + 8) * PSF + c];
            afr[2] = Ps[r * PSF + c + 4];
            afr[3] = Ps[(r + 8) * PSF + c + 4];
            #pragma unroll
            for (int j = 0; j < 8; j++) {
                float bfr[2];
                int key = kk * 8 + t4;
                int d   = j * 8 + gid;
                bfr[0] = Vs[key * VSF + d];
                bfr[1] = Vs[(key + 4) * VSF + d];
                mma_tf32(out[j], afr, bfr);
            }
        }
    }

    float inv0 = 1.0f / lrow[0];
    float inv1 = 1.0f / lrow[1];
    int r0 = wrow + gid;
    #pragma unroll
    for (int j = 0; j < 8; j++) {
        int col = j * 8 + 2 * t4;
        *(float2*)&ctx[qbase + (size_t)r0 * Eq + col] =
            make_float2(out[j][0] * inv0, out[j][1] * inv0);
        *(float2*)&ctx[qbase + (size_t)(r0 + 8) * Eq + col] =
            make_float2(out[j][2] * inv1, out[j][3] * inv1);
    }
}

// ---------------------------------------------------------------------------
// Launch
// ---------------------------------------------------------------------------
extern "C" void kernel_launch(void* const* d_in, const int* in_sizes, int n_in,
                              void* d_out, int out_size)
{
    const float* query = (const float*)d_in[0];
    const float* key_  = (const float*)d_in[1];
    const float* value = (const float*)d_in[2];
    const float* Wqg   = (const float*)d_in[3];
    const float* bqg   = (const float*)d_in[4];
    const float* Wk    = (const float*)d_in[5];
    const float* bk    = (const float*)d_in[6];
    const float* Wv    = (const float*)d_in[7];
    const float* bv    = (const float*)d_in[8];
    const float* Wq_in = (const float*)d_in[9];
    const float* bq_in = (const float*)d_in[10];
    const float* Wk_in = (const float*)d_in[11];
    const float* bk_in = (const float*)d_in[12];
    const float* Wv_in = (const float*)d_in[13];
    const float* bv_in = (const float*)d_in[14];
    const float* Wout  = (const float*)d_in[15];
    const float* bout  = (const float*)d_in[16];
    float* out = (float*)d_out;

    float *wc, *bc, *viP, *ctx;
    __nv_bfloat16 *wcbP, *qibP, *kibP;
    cudaGetSymbolAddress((void**)&wc,   g_wc);
    cudaGetSymbolAddress((void**)&wcbP, g_wcb);
    cudaGetSymbolAddress((void**)&bc,   g_bc);
    cudaGetSymbolAddress((void**)&qibP, g_qib);
    cudaGetSymbolAddress((void**)&kibP, g_kib);
    cudaGetSymbolAddress((void**)&viP,  g_vi);
    cudaGetSymbolAddress((void**)&ctx,  g_ctx);

    // 1) Fused bias compose
    biascomp_all<<<dim3(Eq / 8, 12), 256>>>(Wq_in, Wk_in, Wv_in,
                                            bqg, bk, bv,
                                            bq_in, bk_in, bv_in, bc);

    // 2) Fused weight compose: q->bf16(slot 4+g), k->bf16(slot g), v->f32
    gemm_k<0><<<dim3(Eq / 128, Eq / 128, 12), 128>>>(
        Wq_in, Wk_in, Wv_in, Wqg, Wk, Wv, wc, (float*)wcbP, nullptr);

    // 3) ALL projections in ONE launch (ki/qi bf16 + vi tf32, co-scheduled)
    gemm_proj<<<dim3(Eq / 128, (Bq * Sq) / 128, 12), 128>>>(
        key_, query, value, wcbP, wc, bc, kibP, qibP, viP);

    // 4) Attention (R8-exact mixed flash)
    flash_mixed_kernel<<<dim3(Tq / 64, Hq, Bq * Gq), 128>>>(qibP, kibP, viP, ctx);

    // 5) Output projection + scatter
    gemm_k<2><<<dim3(Eq / 128, (Bq * Tq) / 128, Gq), 128>>>(
        ctx, Wout, bout, nullptr, nullptr, nullptr, out, nullptr, nullptr);
}

// round 16
// speedup vs baseline: 1.0818x; 1.0251x over previous
#include <cuda_runtime.h>
#include <cuda_bf16.h>
#include <cstdint>

// Problem constants
#define Bq 2
#define Sq 2048
#define Eq 768
#define Hq 12
#define Gq 4
#define Dq 64
#define Tq 512   // Sq / Gq

#define EEc  ((size_t)Eq * Eq)
#define BTEc ((size_t)Bq * Tq * Eq)
#define BSEc ((size_t)Bq * Sq * Eq)
#define GBTE ((size_t)Gq * Bq * Tq * Eq)      // 3,145,728 floats
#define MLS  ((size_t)Gq * Bq * Hq * Tq * 2)  // per-split m/l floats

// ---------------------------------------------------------------------------
// Scratch (device globals)
// ---------------------------------------------------------------------------
__device__ float g_wc[4 * EEc];                        // composed f32: v g0..3
__device__ __nv_bfloat16 g_wcb[8 * EEc];               // composed bf16: [k g0..3 | q g0..3]
__device__ float g_bc[12 * Eq];                        // composed biases [q|k|v]
__device__ __nv_bfloat16 g_qib[(size_t)Gq*Bq*Tq*Eq];   // qi bf16
__device__ __nv_bfloat16 g_kib[(size_t)Gq*Bq*Sq*Eq];   // ki bf16
__device__ float g_vi [(size_t)Gq*Bq*Sq*Eq];           // vi fp32
__device__ float g_ctx[GBTE];                          // combined ctx fp32
__device__ float g_op [2 * GBTE];                      // split-K partial outputs
__device__ float g_ml [2 * MLS];                       // split-K (m, l) pairs

// ---------------------------------------------------------------------------
// helpers
// ---------------------------------------------------------------------------
__device__ __forceinline__ float f2tf32(float x) {
    uint32_t r;
    asm("cvt.rna.tf32.f32 %0, %1;" : "=r"(r) : "f"(x));
    return __uint_as_float(r);
}
__device__ __forceinline__ float4 f2tf32_4(float4 v) {
    return make_float4(f2tf32(v.x), f2tf32(v.y), f2tf32(v.z), f2tf32(v.w));
}
__device__ __forceinline__ void mma_tf32(float (&d)[4], const float a[4], const float b[2]) {
    asm volatile(
        "mma.sync.aligned.m16n8k8.row.col.f32.tf32.tf32.f32 "
        "{%0,%1,%2,%3}, {%4,%5,%6,%7}, {%8,%9}, {%0,%1,%2,%3};\n"
        : "+f"(d[0]), "+f"(d[1]), "+f"(d[2]), "+f"(d[3])
        : "r"(__float_as_uint(a[0])), "r"(__float_as_uint(a[1])),
          "r"(__float_as_uint(a[2])), "r"(__float_as_uint(a[3])),
          "r"(__float_as_uint(b[0])), "r"(__float_as_uint(b[1])));
}
__device__ __forceinline__ void mma_bf16(float (&d)[4], const uint32_t a[4], const uint32_t b[2]) {
    asm volatile(
        "mma.sync.aligned.m16n8k16.row.col.f32.bf16.bf16.f32 "
        "{%0,%1,%2,%3}, {%4,%5,%6,%7}, {%8,%9}, {%0,%1,%2,%3};\n"
        : "+f"(d[0]), "+f"(d[1]), "+f"(d[2]), "+f"(d[3])
        : "r"(a[0]), "r"(a[1]), "r"(a[2]), "r"(a[3]),
          "r"(b[0]), "r"(b[1]));
}
__device__ __forceinline__ uint32_t packbf(float lo, float hi) {
    uint32_t r;
    asm("cvt.rn.bf16x2.f32 %0, %1, %2;" : "=r"(r) : "f"(hi), "f"(lo));
    return r;
}

// ---------------------------------------------------------------------------
// tf32 GEMM (compose + out), 128 thr / 4 warps, 128x128 tile, warp 64x64,
// double-buffered smem, one sync per chunk.  (Unchanged from R13.)
// MODE 0 (compose, z 0..11): sel0 wcb_q(bf16), sel1 wcb_k(bf16), sel2 wc_v(f32)
// MODE 2 (out, z 0..3): out = scatter_g(ctx[z] @ Wout[z].T + bout[z])
// ---------------------------------------------------------------------------
#define GS 20
#define WKN 136

template<int MODE>
__global__ __launch_bounds__(128)
void gemm_k(const float* __restrict__ P0, const float* __restrict__ P1,
            const float* __restrict__ P2, const float* __restrict__ P3,
            const float* __restrict__ P4, const float* __restrict__ P5,
            float* __restrict__ O0, float* __restrict__ O1, float* __restrict__ O2)
{
    __shared__ float As[2][128 * GS];
    __shared__ float Ws[2][128 * GS];

    const int z = blockIdx.z;
    const int sel = z >> 2, g = z & 3;

    const float* Ab; const float* Wb; const float* bb = nullptr;
    float* Cb = nullptr; __nv_bfloat16* Cb16 = nullptr;
    bool cmap = false, bfout = false;
    if (MODE == 0) {
        Ab = (sel == 0 ? P0 : sel == 1 ? P1 : P2) + (size_t)g * EEc;
        Wb = (sel == 0 ? P3 : sel == 1 ? P4 : P5);
        if (sel == 2) Cb = O0 + (size_t)g * EEc;
        else {
            bfout = true;
            Cb16 = (__nv_bfloat16*)O1 + (size_t)((sel == 0 ? 4 : 0) + g) * EEc;
        }
    } else {
        Ab = P0 + (size_t)z * BTEc;
        Wb = P1 + (size_t)z * EEc;
        bb = P2 + z * Eq;
        Cb = O0; cmap = true;
    }

    const int m0 = blockIdx.y * 128;
    const int n0 = blockIdx.x * 128;
    const int tid  = threadIdx.x;
    const int wid  = tid >> 5;
    const int lane = tid & 31;
    const int gid  = lane >> 2;
    const int t4   = lane & 3;
    const int wm   = (wid & 1) * 64;
    const int wn   = (wid >> 1) * 64;

    float acc[4][8][4];
    #pragma unroll
    for (int a = 0; a < 4; a++)
        #pragma unroll
        for (int b = 0; b < 8; b++)
            #pragma unroll
            for (int c = 0; c < 4; c++) acc[a][b][c] = 0.f;

    float4 pa[4], pw[4];

    auto loadA = [&](int k0) {
        #pragma unroll
        for (int p = 0; p < 4; p++) {
            int idx = tid + p * 128;
            int row = m0 + (idx >> 2);
            int q = (idx & 3) * 4;
            pa[p] = *(const float4*)&Ab[(size_t)row * Eq + k0 + q];
        }
    };
    auto loadW = [&](int k0) {
        if (MODE != 0) {
            #pragma unroll
            for (int p = 0; p < 4; p++) {
                int idx = tid + p * 128;
                int row = n0 + (idx >> 2);
                int q = (idx & 3) * 4;
                pw[p] = *(const float4*)&Wb[(size_t)row * Eq + k0 + q];
            }
        } else {
            #pragma unroll
            for (int p = 0; p < 4; p++) {
                int idx = tid + p * 128;
                int e  = idx >> 5;
                int jq = (idx & 31) * 4;
                pw[p] = *(const float4*)&Wb[(size_t)(k0 + e) * Eq + n0 + jq];
            }
        }
    };
    auto storeT = [&](int buf) {
        #pragma unroll
        for (int p = 0; p < 4; p++) {
            int idx = tid + p * 128;
            int row = idx >> 2;
            int q = (idx & 3) * 4;
            *(float4*)&As[buf][row * GS + q] = f2tf32_4(pa[p]);
        }
        if (MODE != 0) {
            #pragma unroll
            for (int p = 0; p < 4; p++) {
                int idx = tid + p * 128;
                int row = idx >> 2;
                int q = (idx & 3) * 4;
                *(float4*)&Ws[buf][row * GS + q] = f2tf32_4(pw[p]);
            }
        } else {
            #pragma unroll
            for (int p = 0; p < 4; p++) {
                int idx = tid + p * 128;
                int e  = idx >> 5;
                int jq = (idx & 31) * 4;
                *(float4*)&Ws[buf][e * WKN + jq] = f2tf32_4(pw[p]);
            }
        }
    };
    auto compute = [&](int buf) {
        #pragma unroll
        for (int kk = 0; kk < 2; kk++) {
            float afr[4][4];
            #pragma unroll
            for (int mt = 0; mt < 4; mt++) {
                int r = wm + mt * 16 + gid;
                int c = kk * 8 + t4;
                afr[mt][0] = As[buf][r * GS + c];
                afr[mt][1] = As[buf][(r + 8) * GS + c];
                afr[mt][2] = As[buf][r * GS + c + 4];
                afr[mt][3] = As[buf][(r + 8) * GS + c + 4];
            }
            float bfr[8][2];
            #pragma unroll
            for (int nt = 0; nt < 8; nt++) {
                int r = wn + nt * 8 + gid;
                int c = kk * 8 + t4;
                if (MODE == 0) {
                    bfr[nt][0] = Ws[buf][c * WKN + r];
                    bfr[nt][1] = Ws[buf][(c + 4) * WKN + r];
                } else {
                    bfr[nt][0] = Ws[buf][r * GS + c];
                    bfr[nt][1] = Ws[buf][r * GS + c + 4];
                }
            }
            #pragma unroll
            for (int mt = 0; mt < 4; mt++)
                #pragma unroll
                for (int nt = 0; nt < 8; nt++)
                    mma_tf32(acc[mt][nt], afr[mt], bfr[nt]);
        }
    };

    loadA(0); loadW(0);
    storeT(0);
    __syncthreads();

    int buf = 0;
    const int NCH = Eq / 16;
    for (int c = 0; c < NCH; c++) {
        if (c + 1 < NCH) { loadA((c + 1) * 16); loadW((c + 1) * 16); }
        compute(buf);
        if (c + 1 < NCH) storeT(1 - buf);
        __syncthreads();
        buf ^= 1;
    }

    #pragma unroll
    for (int mt = 0; mt < 4; mt++) {
        int m  = m0 + wm + mt * 16 + gid;
        int m2 = m + 8;
        size_t r0, r1;
        if (cmap) {
            r0 = (size_t)(m  >> 9) * Sq + (size_t)(m  & 511) * Gq + g;
            r1 = (size_t)(m2 >> 9) * Sq + (size_t)(m2 & 511) * Gq + g;
        } else { r0 = (size_t)m; r1 = (size_t)m2; }
        #pragma unroll
        for (int nt = 0; nt < 8; nt++) {
            int n = n0 + wn + nt * 8 + 2 * t4;
            float b0 = 0.f, b1 = 0.f;
            if (bb) { b0 = bb[n]; b1 = bb[n + 1]; }
            if (bfout) {
                *(uint32_t*)&Cb16[r0 * Eq + n] = packbf(acc[mt][nt][0] + b0, acc[mt][nt][1] + b1);
                *(uint32_t*)&Cb16[r1 * Eq + n] = packbf(acc[mt][nt][2] + b0, acc[mt][nt][3] + b1);
            } else {
                *(float2*)&Cb[r0 * Eq + n] = make_float2(acc[mt][nt][0] + b0, acc[mt][nt][1] + b1);
                *(float2*)&Cb[r1 * Eq + n] = make_float2(acc[mt][nt][2] + b0, acc[mt][nt][3] + b1);
            }
        }
    }
}

// ---------------------------------------------------------------------------
// MERGED projection kernel (unchanged from R13) — one launch, z 0..11:
//   z 0..3 : ki (bf16) ; z 4..7 : qi (bf16, y<8, amap) ; z 8..11: vi (tf32)
// ---------------------------------------------------------------------------
#define BS2 24

__global__ __launch_bounds__(128)
void gemm_proj(const float* __restrict__ key_, const float* __restrict__ query,
               const float* __restrict__ value,
               const __nv_bfloat16* __restrict__ Wcb,
               const float* __restrict__ Wcv,
               const float* __restrict__ bc,
               __nv_bfloat16* __restrict__ kib,
               __nv_bfloat16* __restrict__ qib,
               float* __restrict__ vif)
{
    __shared__ __align__(16) float smA[2][128 * GS];
    __shared__ __align__(16) float smW[2][128 * GS];

    const int z = blockIdx.z;
    const int sel = z >> 2, g = z & 3;
    const int NCH = Eq / 16;

    const int m0 = blockIdx.y * 128;
    const int n0 = blockIdx.x * 128;
    const int tid  = threadIdx.x;
    const int wid  = tid >> 5;
    const int lane = tid & 31;
    const int gid  = lane >> 2;
    const int t4   = lane & 3;
    const int wm   = (wid & 1) * 64;
    const int wn   = (wid >> 1) * 64;

    if (sel < 2) {
        if (sel == 1 && blockIdx.y >= 8) return;
        const float* Ab = (sel == 0) ? key_ : query;
        const __nv_bfloat16* Wb = Wcb + (size_t)((sel == 0 ? 0 : 4) + g) * EEc;
        const float* bb = bc + ((sel == 0 ? 4 : 0) + g) * Eq;
        __nv_bfloat16* Cb = (sel == 0) ? (kib + (size_t)g * BSEc)
                                       : (qib + (size_t)g * BTEc);
        const bool amap = (sel == 1);

        float acc[4][8][4];
        #pragma unroll
        for (int a = 0; a < 4; a++)
            #pragma unroll
            for (int b = 0; b < 8; b++)
                #pragma unroll
                for (int c = 0; c < 4; c++) acc[a][b][c] = 0.f;

        float4 pa[4];
        uint2  pw[4];

        auto loadA = [&](int k0) {
            #pragma unroll
            for (int p = 0; p < 4; p++) {
                int idx = tid + p * 128;
                int row = m0 + (idx >> 2);
                int q4 = (idx & 3) * 4;
                size_t gr;
                if (amap) gr = (size_t)(row >> 9) * Sq + (size_t)(row & 511) * Gq + g;
                else      gr = (size_t)row;
                pa[p] = *(const float4*)&Ab[gr * Eq + k0 + q4];
            }
        };
        auto loadW = [&](int k0) {
            #pragma unroll
            for (int p = 0; p < 4; p++) {
                int idx = tid + p * 128;
                int row = n0 + (idx >> 2);
                int q4 = (idx & 3) * 4;
                pw[p] = *(const uint2*)&Wb[(size_t)row * Eq + k0 + q4];
            }
        };
        auto storeT = [&](int buf) {
            __nv_bfloat16* As2 = (__nv_bfloat16*)smA[buf];
            __nv_bfloat16* Ws2 = (__nv_bfloat16*)smW[buf];
            #pragma unroll
            for (int p = 0; p < 4; p++) {
                int idx = tid + p * 128;
                int row = idx >> 2;
                int q4 = (idx & 3) * 4;
                uint2 v;
                v.x = packbf(pa[p].x, pa[p].y);
                v.y = packbf(pa[p].z, pa[p].w);
                *(uint2*)&As2[row * BS2 + q4] = v;
                *(uint2*)&Ws2[row * BS2 + q4] = pw[p];
            }
        };
        auto compute = [&](int buf) {
            const __nv_bfloat16* As2 = (const __nv_bfloat16*)smA[buf];
            const __nv_bfloat16* Ws2 = (const __nv_bfloat16*)smW[buf];
            uint32_t afr[4][4];
            #pragma unroll
            for (int mt = 0; mt < 4; mt++) {
                int r = wm + mt * 16 + gid;
                int c = 2 * t4;
                afr[mt][0] = *(const uint32_t*)&As2[r * BS2 + c];
                afr[mt][1] = *(const uint32_t*)&As2[(r + 8) * BS2 + c];
                afr[mt][2] = *(const uint32_t*)&As2[r * BS2 + c + 8];
                afr[mt][3] = *(const uint32_t*)&As2[(r + 8) * BS2 + c + 8];
            }
            uint32_t bfr[8][2];
            #pragma unroll
            for (int nt = 0; nt < 8; nt++) {
                int r = wn + nt * 8 + gid;
                int c = 2 * t4;
                bfr[nt][0] = *(const uint32_t*)&Ws2[r * BS2 + c];
                bfr[nt][1] = *(const uint32_t*)&Ws2[r * BS2 + c + 8];
            }
            #pragma unroll
            for (int mt = 0; mt < 4; mt++)
                #pragma unroll
                for (int nt = 0; nt < 8; nt++)
                    mma_bf16(acc[mt][nt], afr[mt], bfr[nt]);
        };

        loadA(0); loadW(0);
        storeT(0);
        __syncthreads();
        int buf = 0;
        for (int c = 0; c < NCH; c++) {
            if (c + 1 < NCH) { loadA((c + 1) * 16); loadW((c + 1) * 16); }
            compute(buf);
            if (c + 1 < NCH) storeT(1 - buf);
            __syncthreads();
            buf ^= 1;
        }

        #pragma unroll
        for (int mt = 0; mt < 4; mt++) {
            int m  = m0 + wm + mt * 16 + gid;
            int m2 = m + 8;
            #pragma unroll
            for (int nt = 0; nt < 8; nt++) {
                int n = n0 + wn + nt * 8 + 2 * t4;
                float b0 = bb[n], b1 = bb[n + 1];
                *(uint32_t*)&Cb[(size_t)m  * Eq + n] = packbf(acc[mt][nt][0] + b0, acc[mt][nt][1] + b1);
                *(uint32_t*)&Cb[(size_t)m2 * Eq + n] = packbf(acc[mt][nt][2] + b0, acc[mt][nt][3] + b1);
            }
        }
    } else {
        const float* Ab = value;
        const float* Wb = Wcv + (size_t)g * EEc;
        const float* bb = bc + (8 + g) * Eq;
        float* Cb = vif + (size_t)g * BSEc;

        float acc[4][8][4];
        #pragma unroll
        for (int a = 0; a < 4; a++)
            #pragma unroll
            for (int b = 0; b < 8; b++)
                #pragma unroll
                for (int c = 0; c < 4; c++) acc[a][b][c] = 0.f;

        float4 pa[4], pw[4];

        auto loadA = [&](int k0) {
            #pragma unroll
            for (int p = 0; p < 4; p++) {
                int idx = tid + p * 128;
                int row = m0 + (idx >> 2);
                int q = (idx & 3) * 4;
                pa[p] = *(const float4*)&Ab[(size_t)row * Eq + k0 + q];
            }
        };
        auto loadW = [&](int k0) {
            #pragma unroll
            for (int p = 0; p < 4; p++) {
                int idx = tid + p * 128;
                int row = n0 + (idx >> 2);
                int q = (idx & 3) * 4;
                pw[p] = *(const float4*)&Wb[(size_t)row * Eq + k0 + q];
            }
        };
        auto storeT = [&](int buf) {
            #pragma unroll
            for (int p = 0; p < 4; p++) {
                int idx = tid + p * 128;
                int row = idx >> 2;
                int q = (idx & 3) * 4;
                *(float4*)&smA[buf][row * GS + q] = f2tf32_4(pa[p]);
                *(float4*)&smW[buf][row * GS + q] = f2tf32_4(pw[p]);
            }
        };
        auto compute = [&](int buf) {
            #pragma unroll
            for (int kk = 0; kk < 2; kk++) {
                float afr[4][4];
                #pragma unroll
                for (int mt = 0; mt < 4; mt++) {
                    int r = wm + mt * 16 + gid;
                    int c = kk * 8 + t4;
                    afr[mt][0] = smA[buf][r * GS + c];
                    afr[mt][1] = smA[buf][(r + 8) * GS + c];
                    afr[mt][2] = smA[buf][r * GS + c + 4];
                    afr[mt][3] = smA[buf][(r + 8) * GS + c + 4];
                }
                float bfr[8][2];
                #pragma unroll
                for (int nt = 0; nt < 8; nt++) {
                    int r = wn + nt * 8 + gid;
                    int c = kk * 8 + t4;
                    bfr[nt][0] = smW[buf][r * GS + c];
                    bfr[nt][1] = smW[buf][r * GS + c + 4];
                }
                #pragma unroll
                for (int mt = 0; mt < 4; mt++)
                    #pragma unroll
                    for (int nt = 0; nt < 8; nt++)
                        mma_tf32(acc[mt][nt], afr[mt], bfr[nt]);
            }
        };

        loadA(0); loadW(0);
        storeT(0);
        __syncthreads();
        int buf = 0;
        for (int c = 0; c < NCH; c++) {
            if (c + 1 < NCH) { loadA((c + 1) * 16); loadW((c + 1) * 16); }
            compute(buf);
            if (c + 1 < NCH) storeT(1 - buf);
            __syncthreads();
            buf ^= 1;
        }

        #pragma unroll
        for (int mt = 0; mt < 4; mt++) {
            int m  = m0 + wm + mt * 16 + gid;
            int m2 = m + 8;
            #pragma unroll
            for (int nt = 0; nt < 8; nt++) {
                int n = n0 + wn + nt * 8 + 2 * t4;
                float b0 = bb[n], b1 = bb[n + 1];
                *(float2*)&Cb[(size_t)m  * Eq + n] = make_float2(acc[mt][nt][0] + b0, acc[mt][nt][1] + b1);
                *(float2*)&Cb[(size_t)m2 * Eq + n] = make_float2(acc[mt][nt][2] + b0, acc[mt][nt][3] + b1);
            }
        }
    }
}

// ---------------------------------------------------------------------------
// Fused bias compose (unchanged)
// ---------------------------------------------------------------------------
__global__ void biascomp_all(const float* __restrict__ Wq_in, const float* __restrict__ Wk_in,
                             const float* __restrict__ Wv_in,
                             const float* __restrict__ bqg, const float* __restrict__ bk,
                             const float* __restrict__ bv,
                             const float* __restrict__ bq_in, const float* __restrict__ bk_in,
                             const float* __restrict__ bv_in,
                             float* __restrict__ bc)
{
    int y = blockIdx.y;
    int sel = y >> 2, g = y & 3;
    const float* Win = (sel == 0 ? Wq_in : sel == 1 ? Wk_in : Wv_in) + (size_t)g * EEc;
    const float* bo  = (sel == 0 ? bqg : sel == 1 ? bk : bv);
    const float* bi  = (sel == 0 ? bq_in : sel == 1 ? bk_in : bv_in) + g * Eq;
    int f = blockIdx.x * 8 + (threadIdx.x >> 5);
    int lane = threadIdx.x & 31;
    const float* wr = Win + (size_t)f * Eq;
    float s = 0.f;
    for (int j = lane * 4; j < Eq; j += 128) {
        float4 w = *(const float4*)&wr[j];
        float4 b = *(const float4*)&bo[j];
        s += w.x*b.x + w.y*b.y + w.z*b.z + w.w*b.w;
    }
    #pragma unroll
    for (int o = 16; o; o >>= 1) s += __shfl_xor_sync(0xffffffffu, s, o);
    if (lane == 0) bc[(size_t)y * Eq + f] = s + bi[f];
}

// ---------------------------------------------------------------------------
// Flash attention, SPLIT-K over keys (2 splits of 1024).
// Core loop identical to the proven R8 kernel; differences:
//  - blockIdx.z encodes (zz, split); keys [sp*1024, sp*1024+1024)
//  - skip-rescale: out *= corr only when the running max changed (exact)
//  - epilogue writes UNNORMALIZED out to opart[sp] plus per-row (m, l)
// ---------------------------------------------------------------------------
#define KSB 72
#define VSF 72
#define QSB 72
#define PSF 68

__global__ __launch_bounds__(128)
void flash_split_kernel(const __nv_bfloat16* __restrict__ qi,
                        const __nv_bfloat16* __restrict__ ki,
                        const float* __restrict__ vi,
                        float* __restrict__ opart,
                        float* __restrict__ ml)
{
    __shared__ __align__(16) __nv_bfloat16 Ks[64 * KSB];
    __shared__ __align__(16) float         Vs[64 * VSF];
    __shared__ __align__(16) unsigned char QPbuf[64 * PSF * 4];
    __nv_bfloat16* Qs = (__nv_bfloat16*)QPbuf;
    float*         Ps = (float*)QPbuf;

    const int sp = blockIdx.z & 1;
    const int zz = blockIdx.z >> 1;
    const int h  = blockIdx.y;
    const int t0 = blockIdx.x * 64;
    const size_t qbase = ((size_t)zz * Tq + t0) * Eq + (size_t)h * Dq;
    const size_t kbase = (size_t)zz * Sq * Eq + (size_t)h * Dq;
    float* ob = opart + (size_t)sp * GBTE;
    float* mlb = ml + (size_t)sp * MLS;

    const int tid  = threadIdx.x;
    const int wid  = tid >> 5;
    const int lane = tid & 31;
    const int gid  = lane >> 2;
    const int t4   = lane & 3;
    const int wrow = wid * 16;

    #pragma unroll
    for (int i = 0; i < 4; i++) {
        int idx = tid + i * 128;
        int row = idx >> 3;
        int c8  = idx & 7;
        uint4 v = *(const uint4*)&qi[qbase + (size_t)row * Eq + c8 * 8];
        *(uint2*)&Qs[row * QSB + c8 * 8]     = make_uint2(v.x, v.y);
        *(uint2*)&Qs[row * QSB + c8 * 8 + 4] = make_uint2(v.z, v.w);
    }
    __syncthreads();

    uint32_t Aq[4][4];
    #pragma unroll
    for (int kk = 0; kk < 4; kk++) {
        int r = wrow + gid;
        int c = kk * 16 + 2 * t4;
        Aq[kk][0] = *(const uint32_t*)&Qs[r * QSB + c];
        Aq[kk][1] = *(const uint32_t*)&Qs[(r + 8) * QSB + c];
        Aq[kk][2] = *(const uint32_t*)&Qs[r * QSB + c + 8];
        Aq[kk][3] = *(const uint32_t*)&Qs[(r + 8) * QSB + c + 8];
    }

    float out[8][4];
    #pragma unroll
    for (int j = 0; j < 8; j++)
        #pragma unroll
        for (int c = 0; c < 4; c++) out[j][c] = 0.f;
    float mrow[2] = {-1e30f, -1e30f};
    float lrow[2] = {0.f, 0.f};
    const float kappa = 0.125f * 1.44269504088896340736f;

    const int sbeg = sp * (Sq / 2);
    const int send = sbeg + (Sq / 2);
    for (int s0 = sbeg; s0 < send; s0 += 64) {
        __syncthreads();
        #pragma unroll
        for (int i = 0; i < 4; i++) {
            int idx = tid + i * 128;
            int row = idx >> 3;
            int c8  = idx & 7;
            uint4 v = *(const uint4*)&ki[kbase + (size_t)(s0 + row) * Eq + c8 * 8];
            *(uint2*)&Ks[row * KSB + c8 * 8]     = make_uint2(v.x, v.y);
            *(uint2*)&Ks[row * KSB + c8 * 8 + 4] = make_uint2(v.z, v.w);
        }
        #pragma unroll
        for (int i = 0; i < 8; i++) {
            int idx = tid + i * 128;
            int row = idx >> 4;
            int c4  = idx & 15;
            float4 vv = *(const float4*)&vi[kbase + (size_t)(s0 + row) * Eq + c4 * 4];
            *(float4*)&Vs[row * VSF + c4 * 4] = f2tf32_4(vv);
        }
        __syncthreads();

        float sc[8][4];
        #pragma unroll
        for (int j = 0; j < 8; j++)
            #pragma unroll
            for (int c = 0; c < 4; c++) sc[j][c] = 0.f;
        #pragma unroll
        for (int kk = 0; kk < 4; kk++) {
            #pragma unroll
            for (int j = 0; j < 8; j++) {
                const __nv_bfloat16* kr = &Ks[(j * 8 + gid) * KSB + kk * 16 + 2 * t4];
                uint32_t b[2];
                b[0] = *(const uint32_t*)kr;
                b[1] = *(const uint32_t*)(kr + 8);
                mma_bf16(sc[j], Aq[kk], b);
            }
        }

        #pragma unroll
        for (int j = 0; j < 8; j++)
            #pragma unroll
            for (int c = 0; c < 4; c++) sc[j][c] *= kappa;

        #pragma unroll
        for (int r = 0; r < 2; r++) {
            float mx = -1e30f;
            #pragma unroll
            for (int j = 0; j < 8; j++)
                mx = fmaxf(mx, fmaxf(sc[j][2*r], sc[j][2*r + 1]));
            mx = fmaxf(mx, __shfl_xor_sync(0xffffffffu, mx, 1));
            mx = fmaxf(mx, __shfl_xor_sync(0xffffffffu, mx, 2));
            if (mx > mrow[r]) {
                float corr = exp2f(mrow[r] - mx);
                mrow[r] = mx;
                lrow[r] *= corr;
                #pragma unroll
                for (int j = 0; j < 8; j++) {
                    out[j][2*r]     *= corr;
                    out[j][2*r + 1] *= corr;
                }
            }
            float mn = mrow[r];
            float rs = 0.f;
            #pragma unroll
            for (int j = 0; j < 8; j++) {
                float p0 = exp2f(sc[j][2*r]     - mn);
                float p1 = exp2f(sc[j][2*r + 1] - mn);
                sc[j][2*r]     = p0;
                sc[j][2*r + 1] = p1;
                rs += p0 + p1;
            }
            rs += __shfl_xor_sync(0xffffffffu, rs, 1);
            rs += __shfl_xor_sync(0xffffffffu, rs, 2);
            lrow[r] += rs;
        }

        #pragma unroll
        for (int j = 0; j < 8; j++) {
            int col = j * 8 + 2 * t4;
            *(float2*)&Ps[(wrow + gid) * PSF + col] =
                make_float2(f2tf32(sc[j][0]), f2tf32(sc[j][1]));
            *(float2*)&Ps[(wrow + gid + 8) * PSF + col] =
                make_float2(f2tf32(sc[j][2]), f2tf32(sc[j][3]));
        }
        __syncwarp();

        #pragma unroll
        for (int kk = 0; kk < 8; kk++) {
            float afr[4];
            int r = wrow + gid;
            int c = kk * 8 + t4;
            afr[0] = Ps[r * PSF + c];
            afr[1] = Ps[(r + 8) * PSF + c];
            afr[2] = Ps[r * PSF + c + 4];
            afr[3] = Ps[(r + 8) * PSF + c + 4];
            #pragma unroll
            for (int j = 0; j < 8; j++) {
                float bfr[2];
                int key = kk * 8 + t4;
                int d   = j * 8 + gid;
                bfr[0] = Vs[key * VSF + d];
                bfr[1] = Vs[(key + 4) * VSF + d];
                mma_tf32(out[j], afr, bfr);
            }
        }
    }

    // ---- Epilogue: unnormalized out + (m, l) per row ----
    int r0 = wrow + gid;
    #pragma unroll
    for (int j = 0; j < 8; j++) {
        int col = j * 8 + 2 * t4;
        *(float2*)&ob[qbase + (size_t)r0 * Eq + col] =
            make_float2(out[j][0], out[j][1]);
        *(float2*)&ob[qbase + (size_t)(r0 + 8) * Eq + col] =
            make_float2(out[j][2], out[j][3]);
    }
    if (t4 == 0) {
        size_t mli = ((size_t)(zz * Hq + h) * Tq + (t0 + r0)) * 2;
        mlb[mli]     = mrow[0];
        mlb[mli + 1] = lrow[0];
        size_t mli2 = ((size_t)(zz * Hq + h) * Tq + (t0 + r0 + 8)) * 2;
        mlb[mli2]     = mrow[1];
        mlb[mli2 + 1] = lrow[1];
    }
}

// ---------------------------------------------------------------------------
// Split-K combine: ctx = merge(opart[0], opart[1]) with flash-merge formula.
// One float4 per thread; grid covers GBTE/4.
// ---------------------------------------------------------------------------
__global__ void flash_combine(const float* __restrict__ opart,
                              const float* __restrict__ ml,
                              float* __restrict__ ctx)
{
    size_t idx = (size_t)blockIdx.x * 256 + threadIdx.x;   // float4 index
    size_t e4 = idx * 4;
    int col = (int)(e4 % Eq);
    size_t row = e4 / Eq;            // zz*Tq + t
    int zz = (int)(row / Tq);
    int t  = (int)(row % Tq);
    int h  = col / Dq;

    size_t mli = ((size_t)(zz * Hq + h) * Tq + t) * 2;
    float m0 = ml[mli],       l0 = ml[mli + 1];
    float m1 = ml[MLS + mli], l1 = ml[MLS + mli + 1];
    float M  = fmaxf(m0, m1);
    float c0 = exp2f(m0 - M);
    float c1 = exp2f(m1 - M);
    float inv = 1.0f / (l0 * c0 + l1 * c1);

    float4 o0 = *(const float4*)&opart[e4];
    float4 o1 = *(const float4*)&opart[GBTE + e4];
    float4 r;
    r.x = (o0.x * c0 + o1.x * c1) * inv;
    r.y = (o0.y * c0 + o1.y * c1) * inv;
    r.z = (o0.z * c0 + o1.z * c1) * inv;
    r.w = (o0.w * c0 + o1.w * c1) * inv;
    *(float4*)&ctx[e4] = r;
}

// ---------------------------------------------------------------------------
// Launch
// ---------------------------------------------------------------------------
extern "C" void kernel_launch(void* const* d_in, const int* in_sizes, int n_in,
                              void* d_out, int out_size)
{
    const float* query = (const float*)d_in[0];
    const float* key_  = (const float*)d_in[1];
    const float* value = (const float*)d_in[2];
    const float* Wqg   = (const float*)d_in[3];
    const float* bqg   = (const float*)d_in[4];
    const float* Wk    = (const float*)d_in[5];
    const float* bk    = (const float*)d_in[6];
    const float* Wv    = (const float*)d_in[7];
    const float* bv    = (const float*)d_in[8];
    const float* Wq_in = (const float*)d_in[9];
    const float* bq_in = (const float*)d_in[10];
    const float* Wk_in = (const float*)d_in[11];
    const float* bk_in = (const float*)d_in[12];
    const float* Wv_in = (const float*)d_in[13];
    const float* bv_in = (const float*)d_in[14];
    const float* Wout  = (const float*)d_in[15];
    const float* bout  = (const float*)d_in[16];
    float* out = (float*)d_out;

    float *wc, *bc, *viP, *ctx, *opP, *mlP;
    __nv_bfloat16 *wcbP, *qibP, *kibP;
    cudaGetSymbolAddress((void**)&wc,   g_wc);
    cudaGetSymbolAddress((void**)&wcbP, g_wcb);
    cudaGetSymbolAddress((void**)&bc,   g_bc);
    cudaGetSymbolAddress((void**)&qibP, g_qib);
    cudaGetSymbolAddress((void**)&kibP, g_kib);
    cudaGetSymbolAddress((void**)&viP,  g_vi);
    cudaGetSymbolAddress((void**)&ctx,  g_ctx);
    cudaGetSymbolAddress((void**)&opP,  g_op);
    cudaGetSymbolAddress((void**)&mlP,  g_ml);

    // 1) Fused bias compose
    biascomp_all<<<dim3(Eq / 8, 12), 256>>>(Wq_in, Wk_in, Wv_in,
                                            bqg, bk, bv,
                                            bq_in, bk_in, bv_in, bc);

    // 2) Fused weight compose
    gemm_k<0><<<dim3(Eq / 128, Eq / 128, 12), 128>>>(
        Wq_in, Wk_in, Wv_in, Wqg, Wk, Wv, wc, (float*)wcbP, nullptr);

    // 3) All projections in one launch
    gemm_proj<<<dim3(Eq / 128, (Bq * Sq) / 128, 12), 128>>>(
        key_, query, value, wcbP, wc, bc, kibP, qibP, viP);

    // 4) Split-K flash (2 splits) + combine
    flash_split_kernel<<<dim3(Tq / 64, Hq, Bq * Gq * 2), 128>>>(
        qibP, kibP, viP, opP, mlP);
    flash_combine<<<(unsigned)(GBTE / 4 / 256), 256>>>(opP, mlP, ctx);

    // 5) Output projection + scatter
    gemm_k<2><<<dim3(Eq / 128, (Bq * Tq) / 128, Gq), 128>>>(
        ctx, Wout, bout, nullptr, nullptr, nullptr, out, nullptr, nullptr);
}